// round 14
// baseline (speedup 1.0000x reference)
#include <cuda_runtime.h>
#include <cuda_bf16.h>

#define BB 4
#define NN 256
#define HH 256
#define WW 256
#define HW 65536
#define C4 (HW / 4)           // int4 per channel = 16384

// Persistent scratch (device globals). g_sdone/g_mticket/g_acc are reset by
// the finalize CTA at the end of every run (graph-replay safe); g_cidx and
// g_scale are fully overwritten each run.
__device__ int      g_cidx[BB * NN];
__device__ float    g_scale[BB * NN];
__device__ unsigned g_sdone[BB];       // per-batch scan arrivals (0..256)
__device__ unsigned g_mticket[BB];     // per-batch row tickets
__device__ double   g_acc;
__device__ unsigned g_cnt;             // monotonic; finalize at (cnt&1023)==1023

__device__ __forceinline__ float frcp_approx(float x) {
    float r; asm("rcp.approx.f32 %0, %1;" : "=f"(r) : "f"(x)); return r;
}
__device__ __forceinline__ float mask_mul(int t, float r) {   // t in {0,1}
    return __int_as_float(t * __float_as_int(r));
}
__device__ __forceinline__ unsigned ld_acq(const unsigned* p) {
    unsigned v;
    asm volatile("ld.acquire.gpu.global.u32 %0, [%1];" : "=r"(v) : "l"(p) : "memory");
    return v;
}

// ---------------------------------------------------------------------------
// Fused balanced persistent kernel: 1024 CTAs x 128 threads, all co-resident
// (launch_bounds(128,7) -> 1036 slots >= 1024; smem ~10.3KB*7 fits).
// Phase A: CTA ix scans channel ix (256KB contiguous, branchless identity).
// Phase B: own-batch-first ticketed main rows behind per-batch gates.
// ---------------------------------------------------------------------------
__global__ __launch_bounds__(128, 7) void k_fused(const float* __restrict__ pred,
                                                  const int*   __restrict__ tc,
                                                  const int*   __restrict__ tgt,
                                                  const int*   __restrict__ pad,
                                                  float*       __restrict__ out) {
    __shared__ float2 s_c [NN];
    __shared__ float  s_imp[4][WW];
    __shared__ int    s_ts [4][WW];
    __shared__ int    s_ri[4];
    __shared__ double s_rd[4];
    __shared__ int    s_bcast;

    const int ix   = blockIdx.x;       // 0..1023 == channel id == (b,n)
    const int bx   = ix >> 8;
    const int tid  = threadIdx.x;
    const int lane = tid & 31;
    const int wid  = tid >> 5;

    // ================= Phase A: scan own channel (256KB contiguous) ========
    {
        const int4* p = reinterpret_cast<const int4*>(tc) + (size_t)ix * C4;
        int acc = 0;
        #pragma unroll 8
        for (int i = 0; i < 128; i++) {
            const int li = i * 128 + tid;          // coalesced, in-order stream
            const int4 v = __ldcs(&p[li]);
            const int s  = (v.x + v.y) + (v.z + v.w);
            acc += (li * 4) * s + (v.y + v.z * 2 + v.w * 3);
        }
        #pragma unroll
        for (int o = 16; o; o >>= 1)
            acc += __shfl_down_sync(0xffffffffu, acc, o);
        if (lane == 0) s_ri[wid] = acc;
        __syncthreads();
        if (tid == 0) {
            g_cidx[ix]  = s_ri[0] + s_ri[1] + s_ri[2] + s_ri[3];
            g_scale[ix] = pad[ix] ? 0.0f : 1.0f;
            __threadfence();                       // release before gate count
            atomicAdd(&g_sdone[bx], 1u);
        }
        __syncthreads();                           // protect s_ri / ordering
    }

    // ================= Phase B: ticketed main rows, own batch first ========
    for (int bb = 0; bb < BB; bb++) {
        const int b = (bx + bb) & 3;
        if (tid == 0) {
            while (ld_acq(&g_sdone[b]) < 256u) __nanosleep(64);
        }
        __syncthreads();                           // gate open CTA-wide

        while (true) {
            if (tid == 0) s_bcast = (int)atomicAdd(&g_mticket[b], 1u);
            __syncthreads();
            const int h = s_bcast;
            if (h >= HH) break;

            // ---- per-row center table ----
            #pragma unroll
            for (int k = 0; k < 2; k++) {
                const int n  = tid + k * 128;
                const int ci = g_cidx[b * NN + n];
                const float dr = (float)(h - (ci >> 8));
                float dr2 = dr * dr + 1e-6f;
                if (g_scale[b * NN + n] == 0.0f)
                    dr2 = __int_as_float(0x7f800000);   // +INF -> rcp = +0
                s_c[n] = make_float2(dr2, (float)(ci & 255));
            }
            __syncthreads();

            // ---- verbatim R8 main body ----
            const int part = wid;
            const float w0f = (float)(lane * 4);
            const int4* tp0 = reinterpret_cast<const int4*>(
                                  tgt + (size_t)b * NN * HW + (size_t)h * WW)
                              + (size_t)part * 64 * (HW / 4) + lane;
            const int4* tp1 = tp0 + 32;
            const float2* cp = s_c + part * 64;

            float iA0=0.f,iA1=0.f,iA2=0.f,iA3=0.f, iB0=0.f,iB1=0.f,iB2=0.f,iB3=0.f;
            int tspA = 0, tspB = 0;

            #pragma unroll 4
            for (int j = 0; j < 64; j++) {
                const int4 t0 = __ldcs(tp0 + (size_t)j * (HW / 4));
                const int4 t1 = __ldcs(tp1 + (size_t)j * (HW / 4));
                const float2 c = cp[j];
                const float d0 = w0f - c.y;
                const float d1 = d0 + 1.0f, d2 = d0 + 2.0f, d3 = d0 + 3.0f;
                const float e0 = d0 + 128.0f, e1 = d0 + 129.0f,
                            e2 = d0 + 130.0f, e3 = d0 + 131.0f;

                iA0 += mask_mul(t0.x, frcp_approx(fmaf(d0, d0, c.x)));
                iA1 += mask_mul(t0.y, frcp_approx(fmaf(d1, d1, c.x)));
                iA2 += mask_mul(t0.z, frcp_approx(fmaf(d2, d2, c.x)));
                iA3 += mask_mul(t0.w, frcp_approx(fmaf(d3, d3, c.x)));
                iB0 += mask_mul(t1.x, frcp_approx(fmaf(e0, e0, c.x)));
                iB1 += mask_mul(t1.y, frcp_approx(fmaf(e1, e1, c.x)));
                iB2 += mask_mul(t1.z, frcp_approx(fmaf(e2, e2, c.x)));
                iB3 += mask_mul(t1.w, frcp_approx(fmaf(e3, e3, c.x)));

                tspA += t0.x + t0.y * 256 + t0.z * 65536 + t0.w * 16777216;
                tspB += t1.x + t1.y * 256 + t1.z * 65536 + t1.w * 16777216;
            }

            const int w0 = lane * 4;
            *reinterpret_cast<float4*>(&s_imp[part][w0])       = make_float4(iA0, iA1, iA2, iA3);
            *reinterpret_cast<float4*>(&s_imp[part][w0 + 128]) = make_float4(iB0, iB1, iB2, iB3);
            *reinterpret_cast<int4*>  (&s_ts [part][w0])       =
                make_int4(tspA & 255, (tspA >> 8) & 255, (tspA >> 16) & 255, (tspA >> 24) & 255);
            *reinterpret_cast<int4*>  (&s_ts [part][w0 + 128]) =
                make_int4(tspB & 255, (tspB >> 8) & 255, (tspB >> 16) & 255, (tspB >> 24) & 255);
            __syncthreads();

            double v = 0.0;
            #pragma unroll
            for (int k = 0; k < 2; k++) {
                const int w = tid + k * 128;
                const float imp = s_imp[0][w] + s_imp[1][w] + s_imp[2][w] + s_imp[3][w];
                const int   ts  = s_ts [0][w] + s_ts [1][w] + s_ts [2][w] + s_ts [3][w];
                const float pi  = imp + (float)(~ts) * 0.5f;
                const float x   = pred[((size_t)b * HH + h) * WW + w];
                const float bce = fmaxf(x, 0.0f) - x * (float)ts + log1pf(expf(-fabsf(x)));
                v += (double)(bce * pi);
            }
            #pragma unroll
            for (int o = 16; o; o >>= 1) v += __shfl_down_sync(0xffffffffu, v, o);
            if (lane == 0) s_rd[wid] = v;
            __syncthreads();
            if (tid == 0)
                atomicAdd(&g_acc, s_rd[0] + s_rd[1] + s_rd[2] + s_rd[3]);
            __syncthreads();                       // protect smem reuse
        }
    }

    // ================= Finalize (last CTA of this run) ======================
    if (tid == 0) {
        __threadfence();
        const unsigned done = atomicAdd(&g_cnt, 1u);
        s_bcast = ((done & 1023u) == 1023u) ? 1 : 0;
    }
    __syncthreads();
    if (s_bcast && tid == 0) {
        __threadfence();
        const double total = atomicAdd(&g_acc, 0.0);   // coherent read
        out[0] = (float)(total * (1.0 / (double)(BB * HW)));
        g_acc = 0.0;
        #pragma unroll
        for (int i = 0; i < BB; i++) { g_mticket[i] = 0u; g_sdone[i] = 0u; }
        __threadfence();
    }
}

// ---------------------------------------------------------------------------
// inputs (metadata order): predictions f32[4,256,256], target_centers i32[4,256,256,256],
//                          targets i32[4,256,256,256], pad_mask (bool->int32)[4,256]
// output: f32 scalar
// ---------------------------------------------------------------------------
extern "C" void kernel_launch(void* const* d_in, const int* in_sizes, int n_in,
                              void* d_out, int out_size) {
    const float* pred = (const float*)d_in[0];
    const int*   tc   = (const int*)d_in[1];
    const int*   tgt  = (const int*)d_in[2];
    const int*   pad  = (const int*)d_in[3];
    float* out = (float*)d_out;

    k_fused<<<BB * NN, 128>>>(pred, tc, tgt, pad, out);
}

// round 15
// speedup vs baseline: 1.0986x; 1.0986x over previous
#include <cuda_runtime.h>
#include <cuda_bf16.h>

#define BB 4
#define NN 256
#define HH 256
#define WW 256
#define HW 65536   // HH*WW

// Scratch (device globals — no allocations allowed)
__device__ int      g_cidx[BB * NN];    // flat center index within HxW for each (b,n)
__device__ float    g_scale[BB * NN];   // 0.0f if pad_mask[b,n] else 1.0f
__device__ double   g_acc;              // global sum accumulator
__device__ unsigned g_cnt;              // blocks-done counter for last-block finalize

__device__ __forceinline__ float frcp_approx(float x) {
    float r; asm("rcp.approx.f32 %0, %1;" : "=f"(r) : "f"(x)); return r;
}
// branchless: t in {0,1} -> returns r when t==1, +0.0f when t==0 (IMAD, no branch)
__device__ __forceinline__ float mask_mul(int t, float r) {
    return __int_as_float(t * __float_as_int(r));
}

// ---------------------------------------------------------------------------
// Kernel 1: locate the (unique) 1 per (b,n) channel WITHOUT branches.
// Exactly one element is 1, all others 0, so the flat index equals
//   sum_i [ 4*idx4_i*(vx+vy+vz+vw) + (vy + 2*vz + 3*vw) ]
// Pure IMAD/IADD inner loop (no BSSY/BSYNC), then a block sum-reduce.
// Measured ~38.3us = ~7.0 TB/s (practical DRAM ceiling for this pattern).
// ---------------------------------------------------------------------------
__global__ __launch_bounds__(256) void k_centers(const int* __restrict__ tc,
                                                 const int* __restrict__ pad) {
    const int bn  = blockIdx.x;
    const int tid = threadIdx.x;
    if (bn == 0 && tid == 0) { g_acc = 0.0; g_cnt = 0u; }
    if (tid == 0) g_scale[bn] = pad[bn] ? 0.0f : 1.0f;

    const int4* p = reinterpret_cast<const int4*>(tc) + (size_t)bn * (HW / 4);
    int acc = 0;
    #pragma unroll 8
    for (int i = 0; i < 64; i++) {
        const int idx4 = i * 256 + tid;          // coalesced: warp reads 512B
        const int4 v = __ldcs(&p[idx4]);         // streaming: no reuse
        const int s  = (v.x + v.y) + (v.z + v.w);
        acc += (idx4 * 4) * s + (v.y + v.z * 2 + v.w * 3);
    }

    #pragma unroll
    for (int off = 16; off; off >>= 1)
        acc += __shfl_down_sync(0xffffffffu, acc, off);
    __shared__ int sred[8];
    if ((tid & 31) == 0) sred[tid >> 5] = acc;
    __syncthreads();
    if (tid < 8) {
        acc = sred[tid];
        acc += __shfl_down_sync(0xffu, acc, 4);
        acc += __shfl_down_sync(0xffu, acc, 2);
        acc += __shfl_down_sync(0xffu, acc, 1);
        if (tid == 0) g_cidx[bn] = acc;
    }
}

// ---------------------------------------------------------------------------
// Kernel 2: main fused pass + finalize — champion R8 configuration.
// grid = 1024 (one per (b,h) row), block = 128 threads, 7 CTAs/SM resident
// -> all 1024 CTAs in one wave. 4 warps = 4 n-partitions (64 n each); each
// thread owns 8 pixels: quad0 at w=4*lane, quad1 at w=4*lane+128 (two
// independent int4 loads/iter). Per-pixel denominator via single FMA (exact
// epsilon); pad folded into dr2 as +INF (rcp.approx(INF)=+0); branchless
// integer-mask accumulate; ts counts byte-packed. Measured ~45.0us.
// ---------------------------------------------------------------------------
__global__ __launch_bounds__(128, 7) void k_main(const float* __restrict__ pred,
                                                 const int*   __restrict__ tgt,
                                                 float*       __restrict__ out) {
    __shared__ float2 s_c [NN];      // (dr2eff, ccf)
    __shared__ float  s_imp[4][WW];  // per-partition importance partials
    __shared__ int    s_ts [4][WW];  // per-partition target-sum partials

    const int b   = blockIdx.x >> 8;   // grid = BB*HH = 1024
    const int h   = blockIdx.x & 255;
    const int tid = threadIdx.x;

    #pragma unroll
    for (int k = 0; k < 2; k++) {
        const int n  = tid + k * 128;
        const int ci = g_cidx[b * NN + n];
        const float dr = (float)(h - (ci >> 8));       // WW == 256
        float dr2 = dr * dr + 1e-6f;
        if (g_scale[b * NN + n] == 0.0f)
            dr2 = __int_as_float(0x7f800000);          // +INF -> rcp = +0
        s_c[n] = make_float2(dr2, (float)(ci & 255));
    }
    __syncthreads();

    const int lane = tid & 31;
    const int part = tid >> 5;          // warp = n-partition 0..3
    const float w0f = (float)(lane * 4);

    const int4* tp0 = reinterpret_cast<const int4*>(
                          tgt + (size_t)b * NN * HW + (size_t)h * WW)
                      + (size_t)part * 64 * (HW / 4) + lane;
    const int4* tp1 = tp0 + 32;
    const float2* cp = s_c + part * 64;

    float impA0 = 0.f, impA1 = 0.f, impA2 = 0.f, impA3 = 0.f;   // quad0
    float impB0 = 0.f, impB1 = 0.f, impB2 = 0.f, impB3 = 0.f;   // quad1
    int   tspA = 0, tspB = 0;                                    // byte-packed counts

    #pragma unroll 4
    for (int j = 0; j < 64; j++) {
        const int4 t0 = __ldcs(tp0 + (size_t)j * (HW / 4));   // independent
        const int4 t1 = __ldcs(tp1 + (size_t)j * (HW / 4));   // independent
        const float2 c = cp[j];
        const float d0 = w0f - c.y;           // exact small integers in fp32
        const float d1 = d0 + 1.0f;
        const float d2 = d0 + 2.0f;
        const float d3 = d0 + 3.0f;
        const float e0 = d0 + 128.0f;
        const float e1 = d0 + 129.0f;
        const float e2 = d0 + 130.0f;
        const float e3 = d0 + 131.0f;

        impA0 += mask_mul(t0.x, frcp_approx(fmaf(d0, d0, c.x)));
        impA1 += mask_mul(t0.y, frcp_approx(fmaf(d1, d1, c.x)));
        impA2 += mask_mul(t0.z, frcp_approx(fmaf(d2, d2, c.x)));
        impA3 += mask_mul(t0.w, frcp_approx(fmaf(d3, d3, c.x)));
        impB0 += mask_mul(t1.x, frcp_approx(fmaf(e0, e0, c.x)));
        impB1 += mask_mul(t1.y, frcp_approx(fmaf(e1, e1, c.x)));
        impB2 += mask_mul(t1.z, frcp_approx(fmaf(e2, e2, c.x)));
        impB3 += mask_mul(t1.w, frcp_approx(fmaf(e3, e3, c.x)));

        tspA += t0.x + t0.y * 256 + t0.z * 65536 + t0.w * 16777216;
        tspB += t1.x + t1.y * 256 + t1.z * 65536 + t1.w * 16777216;
    }

    // vector stores of partials (16B-aligned)
    const int w0 = lane * 4;
    *reinterpret_cast<float4*>(&s_imp[part][w0])       = make_float4(impA0, impA1, impA2, impA3);
    *reinterpret_cast<float4*>(&s_imp[part][w0 + 128]) = make_float4(impB0, impB1, impB2, impB3);
    *reinterpret_cast<int4*>  (&s_ts [part][w0])       =
        make_int4(tspA & 255, (tspA >> 8) & 255, (tspA >> 16) & 255, (tspA >> 24) & 255);
    *reinterpret_cast<int4*>  (&s_ts [part][w0 + 128]) =
        make_int4(tspB & 255, (tspB >> 8) & 255, (tspB >> 16) & 255, (tspB >> 24) & 255);
    __syncthreads();

    // each thread finalizes 2 pixels: w = tid and w = tid + 128
    double v = 0.0;
    #pragma unroll
    for (int k = 0; k < 2; k++) {
        const int w = tid + k * 128;
        const float imp = s_imp[0][w] + s_imp[1][w] + s_imp[2][w] + s_imp[3][w];
        const int   ts  = s_ts [0][w] + s_ts [1][w] + s_ts [2][w] + s_ts [3][w];

        // importance_coeff = ~tsum * 0.5  (bitwise invert: -ts-1)
        const float pi = imp + (float)(~ts) * 0.5f;

        const float x = pred[((size_t)b * HH + h) * WW + w];
        const float z = (float)ts;
        const float bce = fmaxf(x, 0.0f) - x * z + log1pf(expf(-fabsf(x)));
        v += (double)(bce * pi);
    }

    // warp reduce (double)
    #pragma unroll
    for (int off = 16; off; off >>= 1)
        v += __shfl_down_sync(0xffffffffu, v, off);

    __shared__ double s_red[4];
    if (lane == 0) s_red[part] = v;
    __syncthreads();
    if (tid < 4) {
        v = s_red[tid];
        v += __shfl_down_sync(0xfu, v, 2);
        v += __shfl_down_sync(0xfu, v, 1);
        if (tid == 0) {
            atomicAdd(&g_acc, v);
            __threadfence();
            const unsigned done = atomicAdd(&g_cnt, 1u);
            if (done == (unsigned)gridDim.x - 1u) {
                const double total = atomicAdd(&g_acc, 0.0);  // coherent read
                out[0] = (float)(total * (1.0 / (double)(BB * HW)));
            }
        }
    }
}

// ---------------------------------------------------------------------------
// inputs (metadata order): predictions f32[4,256,256], target_centers i32[4,256,256,256],
//                          targets i32[4,256,256,256], pad_mask (bool->int32)[4,256]
// output: f32 scalar
// ---------------------------------------------------------------------------
extern "C" void kernel_launch(void* const* d_in, const int* in_sizes, int n_in,
                              void* d_out, int out_size) {
    const float* pred = (const float*)d_in[0];
    const int*   tc   = (const int*)d_in[1];
    const int*   tgt  = (const int*)d_in[2];
    const int*   pad  = (const int*)d_in[3];
    float* out = (float*)d_out;

    k_centers<<<BB * NN, 256>>>(tc, pad);
    k_main<<<BB * HH, 128>>>(pred, tgt, out);
}